// round 14
// baseline (speedup 1.0000x reference)
#include <cuda_runtime.h>
#include <cstdint>

// SphConv, tf32 mma.sync. o32 warps (4/CTA), TWO x-tiles (4 batches) per CTA
// with weight registers hoisted across tiles: weights/batch 160KB -> 96KB.
// lg-grouped rows, overlapping m16 blocks, descending-lg transpose epilogue
// (high-block-first within lg), coalesced final STG. K-eighth weight staging.

#define NCOEF 45
#define BSTRIDE (128 * NCOEF)
#define XROW 132                        // MMA-phase row stride (528B)
#define TROW 133                        // transpose-phase row stride
#define TILE_STRIDE 11972               // 90*133=11970 padded to 16B multiple
#define SMEM_BYTES (2 * TILE_STRIDE * 4)  // 95776 -> 2 CTAs/SM

__device__ float4 g_wpB[5 * 16 * 8 * 32];

__global__ void prep_w(const float* __restrict__ w) {
    int idx  = blockIdx.x * blockDim.x + threadIdx.x;   // 20480 exactly
    int lane = idx & 31;
    int ks2  = (idx >> 5) & 7;
    int nb   = (idx >> 8) & 15;
    int lg   = idx >> 12;
    int o    = nb * 8 + (lane >> 2);
    int i0   = ks2 * 16 + (lane & 3);
    float l  = 2.0f * (float)lg;
    float s  = 6.28318530717958647692f *
               sqrtf(12.5663706143591729539f / (2.0f * l + 1.0f)) * (1.0f / 128.0f);
    float4 v;
    v.x = w[(o * 128 + i0) * 5 + lg] * s;
    v.y = w[(o * 128 + i0 + 4) * 5 + lg] * s;
    v.z = w[(o * 128 + i0 + 8) * 5 + lg] * s;
    v.w = w[(o * 128 + i0 + 12) * 5 + lg] * s;
    asm("cvt.rna.tf32.f32 %0, %0;" : "+f"(v.x));
    asm("cvt.rna.tf32.f32 %0, %0;" : "+f"(v.y));
    asm("cvt.rna.tf32.f32 %0, %0;" : "+f"(v.z));
    asm("cvt.rna.tf32.f32 %0, %0;" : "+f"(v.w));
    g_wpB[idx] = v;
}

__device__ __forceinline__ uint32_t smem_u32(const void* p) {
    uint32_t a;
    asm("{ .reg .u64 t; cvta.to.shared.u64 t, %1; cvt.u32.u64 %0, t; }" : "=r"(a) : "l"(p));
    return a;
}
__device__ __forceinline__ void ldsm4(uint32_t* r, uint32_t addr) {
    asm volatile("ldmatrix.sync.aligned.m8n8.x4.shared.b16 {%0,%1,%2,%3}, [%4];"
                 : "=r"(r[0]), "=r"(r[1]), "=r"(r[2]), "=r"(r[3]) : "r"(addr));
}
__device__ __forceinline__ void mma4(float* d, const uint32_t* a,
                                     uint32_t b0, uint32_t b1) {
    asm volatile(
        "mma.sync.aligned.m16n8k8.row.col.f32.tf32.tf32.f32 "
        "{%0,%1,%2,%3}, {%4,%5,%6,%7}, {%8,%9}, {%0,%1,%2,%3};"
        : "+f"(d[0]), "+f"(d[1]), "+f"(d[2]), "+f"(d[3])
        : "r"(a[0]), "r"(a[1]), "r"(a[2]), "r"(a[3]), "r"(b0), "r"(b1));
}

// One lg-run: L overlapping m16 blocks, BOTH tiles, K-eighth weight staging.
// Ends: sync + 133-stride acc dump (predicated to [GLO2, GHI2)).
template <int LG, int L, int B0, int B1>
__device__ __forceinline__ void do_run(float* Xs, uint32_t sA,
                                       const float4* pw4, int wid, int lr, int lc) {
    constexpr int BASES[2] = {B0, B1};
    constexpr int GLO  = 2 * LG * LG - LG;
    constexpr int GLEN = 4 * LG + 1;
    constexpr int GLO2 = 2 * GLO;
    constexpr int GHI2 = GLO2 + 2 * GLEN;

    const float4* pw = pw4 + LG * 4096;

    float acc[2][L][4][4];
    #pragma unroll
    for (int t = 0; t < 2; t++)
        #pragma unroll
        for (int j = 0; j < L; j++)
            #pragma unroll
            for (int nb = 0; nb < 4; nb++)
                #pragma unroll
                for (int e = 0; e < 4; e++) acc[t][j][nb][e] = 0.0f;

    #pragma unroll
    for (int s = 0; s < 8; s++) {
        float4 w4[4];
        #pragma unroll
        for (int nb = 0; nb < 4; nb++) w4[nb] = pw[nb * 256 + s * 32];

        #pragma unroll
        for (int t = 0; t < 2; t++) {
            #pragma unroll
            for (int j = 0; j < L; j++) {
                const uint32_t ab = sA + (uint32_t)(t * (TILE_STRIDE * 4))
                                    + (uint32_t)(BASES[j] * (XROW * 4));
                uint32_t a0[4], a1[4];
                ldsm4(a0, ab + (uint32_t)((2 * s) * 32));
                ldsm4(a1, ab + (uint32_t)((2 * s + 1) * 32));
                #pragma unroll
                for (int nb = 0; nb < 4; nb++) {
                    mma4(acc[t][j][nb], a0, __float_as_uint(w4[nb].x),
                                            __float_as_uint(w4[nb].y));
                    mma4(acc[t][j][nb], a1, __float_as_uint(w4[nb].z),
                                            __float_as_uint(w4[nb].w));
                }
            }
        }
    }

    __syncthreads();   // all warps done ldsm-reading this run's rows

    #pragma unroll
    for (int t = 0; t < 2; t++) {
        #pragma unroll
        for (int j = 0; j < L; j++) {
            #pragma unroll
            for (int hh = 0; hh < 2; hh++) {
                const int g = BASES[j] + lr + hh * 8;
                if (g >= GLO2 && g < GHI2) {
                    float* p = Xs + t * TILE_STRIDE + g * TROW + wid * 32 + 2 * lc;
                    #pragma unroll
                    for (int nb = 0; nb < 4; nb++) {
                        p[nb * 8]     = acc[t][j][nb][hh * 2];
                        p[nb * 8 + 1] = acc[t][j][nb][hh * 2 + 1];
                    }
                }
            }
        }
    }
}

__global__ void __launch_bounds__(128, 2)
sph_r14(const float* __restrict__ x, float* __restrict__ out) {
    extern __shared__ __align__(16) float Xs[];
    __shared__ int rowTab[90];
    const int tid = threadIdx.x;
    const int lane = tid & 31, wid = tid >> 5;

    if (tid < 90) {
        const int b = tid / 45, k = tid - b * 45;
        const int lg = (k >= 28) ? 4 : (k >= 15) ? 3 : (k >= 6) ? 2
                                   : (k >= 1) ? 1 : 0;
        rowTab[tid] = k + (2 * lg * lg - lg) + b * (4 * lg + 1);
    }
    __syncthreads();

    // ---- fill 2 tiles (4 batches): batched LDG (MLP 15) -> cvt -> STS ----
    {
        const float* src = x + (size_t)blockIdx.x * 4 * BSTRIDE + tid;
        int k = tid % 45, i = tid / 45, bb = 0;
        #pragma unroll
        for (int batch = 0; batch < 12; batch++) {
            float v[15];
            #pragma unroll
            for (int u = 0; u < 15; u++)
                v[u] = __ldg(src + (size_t)(batch * 15 + u) * 128);
            #pragma unroll
            for (int u = 0; u < 15; u++) {
                float val = v[u];
                asm("cvt.rna.tf32.f32 %0, %0;" : "+f"(val));
                Xs[(bb >> 1) * TILE_STRIDE
                   + rowTab[(bb & 1) * 45 + k] * XROW + i] = val;
                k += 38; i += 2;                   // advance by 128
                if (k >= 45) { k -= 45; i += 1; }
                if (i >= 128) { i -= 128; bb += 1; }
            }
        }
    }
    __syncthreads();

    const int lr = lane >> 2, lc = lane & 3;
    const uint32_t sbase = smem_u32(Xs);
    const uint32_t sA = sbase + (uint32_t)(((lane & 15) * XROW) * 4
                                           + ((lane >> 4) << 4));
    const float4* pw4 = g_wpB + (size_t)(wid * 4) * 256 + lane;

    // descending lg; within lg: higher blocks first (dump stays above reads)
    do_run<4, 2, 72, 74>(Xs, sA, pw4, wid, lr, lc);
    do_run<4, 1, 56, 56>(Xs, sA, pw4, wid, lr, lc);
    do_run<3, 2, 30, 40>(Xs, sA, pw4, wid, lr, lc);
    do_run<2, 2, 12, 14>(Xs, sA, pw4, wid, lr, lc);
    do_run<1, 1, 2,  2 >(Xs, sA, pw4, wid, lr, lc);
    do_run<0, 1, 0,  0 >(Xs, sA, pw4, wid, lr, lc);
    __syncthreads();

    // ---- coalesced linear STG: warp wid owns batch wid ----
    {
        const float* Xt = Xs + (wid >> 1) * TILE_STRIDE;
        const int* tabB = rowTab + (wid & 1) * 45;
        float* ob = out + (size_t)(blockIdx.x * 4 + wid) * BSTRIDE;
        int k = lane, o = 0;
        #pragma unroll 5
        for (int it = 0; it < 180; it++) {
            ob[it * 32 + lane] = Xt[tabB[k] * TROW + o];
            k += 32;
            if (k >= 45) { k -= 45; o += 1; }
        }
    }
}

extern "C" void kernel_launch(void* const* d_in, const int* in_sizes, int n_in,
                              void* d_out, int out_size) {
    const float* x = (const float*)d_in[0];   // [16384, 128, 45] f32
    const float* w = (const float*)d_in[1];   // [128, 128, 5]   f32
    float* out = (float*)d_out;

    cudaFuncSetAttribute(sph_r14, cudaFuncAttributeMaxDynamicSharedMemorySize,
                         SMEM_BYTES);

    prep_w<<<80, 256>>>(w);
    sph_r14<<<4096, 128, SMEM_BYTES>>>(x, out);
}

// round 15
// speedup vs baseline: 1.1189x; 1.1189x over previous
#include <cuda_runtime.h>
#include <cstdint>

// SphConv, tf32 mma.sync. r12 structure (4 o32-warps, 2 batches, lg-grouped
// rows, rowTab decode, descending-lg transpose epilogue, coalesced STG) with
// a register diet: L<=2 runs, K-eighth weight staging, sequential per-block
// fragments. Goal: no spills at launch_bounds(128,4).

#define NCOEF 45
#define BSTRIDE (128 * NCOEF)
#define XROW 132                        // MMA-phase row stride (528B)
#define TROW 133                        // transpose-phase row stride
#define SMEM_FLOATS 11970               // 90*133 -> 47880 B static

__device__ float4 g_wpB[5 * 16 * 8 * 32];

__global__ void prep_w(const float* __restrict__ w) {
    int idx  = blockIdx.x * blockDim.x + threadIdx.x;   // 20480 exactly
    int lane = idx & 31;
    int ks2  = (idx >> 5) & 7;
    int nb   = (idx >> 8) & 15;
    int lg   = idx >> 12;
    int o    = nb * 8 + (lane >> 2);
    int i0   = ks2 * 16 + (lane & 3);
    float l  = 2.0f * (float)lg;
    float s  = 6.28318530717958647692f *
               sqrtf(12.5663706143591729539f / (2.0f * l + 1.0f)) * (1.0f / 128.0f);
    float4 v;
    v.x = w[(o * 128 + i0) * 5 + lg] * s;
    v.y = w[(o * 128 + i0 + 4) * 5 + lg] * s;
    v.z = w[(o * 128 + i0 + 8) * 5 + lg] * s;
    v.w = w[(o * 128 + i0 + 12) * 5 + lg] * s;
    asm("cvt.rna.tf32.f32 %0, %0;" : "+f"(v.x));
    asm("cvt.rna.tf32.f32 %0, %0;" : "+f"(v.y));
    asm("cvt.rna.tf32.f32 %0, %0;" : "+f"(v.z));
    asm("cvt.rna.tf32.f32 %0, %0;" : "+f"(v.w));
    g_wpB[idx] = v;
}

__device__ __forceinline__ uint32_t smem_u32(const void* p) {
    uint32_t a;
    asm("{ .reg .u64 t; cvta.to.shared.u64 t, %1; cvt.u32.u64 %0, t; }" : "=r"(a) : "l"(p));
    return a;
}
__device__ __forceinline__ void ldsm4(uint32_t* r, uint32_t addr) {
    asm volatile("ldmatrix.sync.aligned.m8n8.x4.shared.b16 {%0,%1,%2,%3}, [%4];"
                 : "=r"(r[0]), "=r"(r[1]), "=r"(r[2]), "=r"(r[3]) : "r"(addr));
}
__device__ __forceinline__ void mma4(float* d, const uint32_t* a,
                                     uint32_t b0, uint32_t b1) {
    asm volatile(
        "mma.sync.aligned.m16n8k8.row.col.f32.tf32.tf32.f32 "
        "{%0,%1,%2,%3}, {%4,%5,%6,%7}, {%8,%9}, {%0,%1,%2,%3};"
        : "+f"(d[0]), "+f"(d[1]), "+f"(d[2]), "+f"(d[3])
        : "r"(a[0]), "r"(a[1]), "r"(a[2]), "r"(a[3]), "r"(b0), "r"(b1));
}

// One lg-run: L (<=2) overlapping m16 blocks, o32 warp, K-eighth weight
// staging, sequential per-block fragments. Ends: sync + 133-stride acc dump.
template <int LG, int L, int B0, int B1>
__device__ __forceinline__ void do_run(float* Xs, uint32_t sA,
                                       const float4* pw4, int wid, int lr, int lc) {
    constexpr int BASES[2] = {B0, B1};
    constexpr int GLO  = 2 * LG * LG - LG;
    constexpr int GLEN = 4 * LG + 1;
    constexpr int GLO2 = 2 * GLO;
    constexpr int GHI2 = GLO2 + 2 * GLEN;

    const float4* pw = pw4 + LG * 4096;

    float acc[L][4][4];
    #pragma unroll
    for (int j = 0; j < L; j++)
        #pragma unroll
        for (int nb = 0; nb < 4; nb++)
            #pragma unroll
            for (int e = 0; e < 4; e++) acc[j][nb][e] = 0.0f;

    #pragma unroll
    for (int s = 0; s < 8; s++) {
        float4 w4[4];
        #pragma unroll
        for (int nb = 0; nb < 4; nb++) w4[nb] = pw[nb * 256 + s * 32];

        #pragma unroll
        for (int j = 0; j < L; j++) {
            const uint32_t ab = sA + (uint32_t)(BASES[j] * (XROW * 4));
            uint32_t a0[4], a1[4];
            ldsm4(a0, ab + (uint32_t)((2 * s) * 32));
            ldsm4(a1, ab + (uint32_t)((2 * s + 1) * 32));
            #pragma unroll
            for (int nb = 0; nb < 4; nb++) {
                mma4(acc[j][nb], a0, __float_as_uint(w4[nb].x),
                                     __float_as_uint(w4[nb].y));
                mma4(acc[j][nb], a1, __float_as_uint(w4[nb].z),
                                     __float_as_uint(w4[nb].w));
            }
        }
    }

    __syncthreads();   // all warps done ldsm-reading before re-striping rows

    #pragma unroll
    for (int j = 0; j < L; j++) {
        #pragma unroll
        for (int hh = 0; hh < 2; hh++) {
            const int g = BASES[j] + lr + hh * 8;
            if (g >= GLO2 && g < GHI2) {
                float* p = Xs + g * TROW + wid * 32 + 2 * lc;
                #pragma unroll
                for (int nb = 0; nb < 4; nb++) {
                    p[nb * 8]     = acc[j][nb][hh * 2];
                    p[nb * 8 + 1] = acc[j][nb][hh * 2 + 1];
                }
            }
        }
    }
}

__global__ void __launch_bounds__(128, 4)
sph_r15(const float* __restrict__ x, float* __restrict__ out) {
    __shared__ __align__(16) float Xs[SMEM_FLOATS];
    __shared__ int rowTab[90];
    const int tid = threadIdx.x;
    const int lane = tid & 31, wid = tid >> 5;

    if (tid < 90) {
        const int b = tid / 45, k = tid - b * 45;
        const int lg = (k >= 28) ? 4 : (k >= 15) ? 3 : (k >= 6) ? 2
                                   : (k >= 1) ? 1 : 0;
        rowTab[tid] = k + (2 * lg * lg - lg) + b * (4 * lg + 1);
    }
    __syncthreads();

    // ---- fill: batched LDG (MLP 15) -> cvt.rna -> table-decoded STS ----
    {
        const float* src = x + (size_t)blockIdx.x * 2 * BSTRIDE + tid;
        int k = tid % 45, i = tid / 45, b_l = 0;
        #pragma unroll
        for (int batch = 0; batch < 6; batch++) {
            float v[15];
            #pragma unroll
            for (int u = 0; u < 15; u++)
                v[u] = __ldg(src + (size_t)(batch * 15 + u) * 128);
            #pragma unroll
            for (int u = 0; u < 15; u++) {
                float val = v[u];
                asm("cvt.rna.tf32.f32 %0, %0;" : "+f"(val));
                Xs[rowTab[b_l * 45 + k] * XROW + i] = val;
                k += 38; i += 2;                   // advance by 128
                if (k >= 45) { k -= 45; i += 1; }
                if (i >= 128) { i -= 128; b_l = 1; }
            }
        }
    }
    __syncthreads();

    const int lr = lane >> 2, lc = lane & 3;
    const uint32_t sbase = smem_u32(Xs);
    const uint32_t sA = sbase + (uint32_t)(((lane & 15) * XROW) * 4
                                           + ((lane >> 4) << 4));
    const float4* pw4 = g_wpB + (size_t)(wid * 4) * 256 + lane;

    // descending lg; within lg: higher blocks first (dump stays above all
    // 132-stride rows that later runs still STORE).
    do_run<4, 2, 72, 74>(Xs, sA, pw4, wid, lr, lc);
    do_run<4, 1, 56, 56>(Xs, sA, pw4, wid, lr, lc);
    do_run<3, 2, 30, 40>(Xs, sA, pw4, wid, lr, lc);
    do_run<2, 2, 12, 14>(Xs, sA, pw4, wid, lr, lc);
    do_run<1, 1, 2,  2 >(Xs, sA, pw4, wid, lr, lc);
    do_run<0, 1, 0,  0 >(Xs, sA, pw4, wid, lr, lc);
    __syncthreads();

    // ---- coalesced linear STG: warp owns batch (wid>>1), o-half (wid&1) ----
    {
        const int b = wid >> 1;
        const int o_base = (wid & 1) * 64;
        float* ob = out + (size_t)blockIdx.x * 2 * BSTRIDE
                    + (size_t)b * BSTRIDE + o_base * NCOEF;
        const int* tabB = rowTab + b * 45;
        int k = lane, o = 0;
        #pragma unroll 5
        for (int it = 0; it < 90; it++) {
            ob[it * 32 + lane] = Xs[tabB[k] * TROW + o_base + o];
            k += 32;
            if (k >= 45) { k -= 45; o += 1; }
        }
    }
}

extern "C" void kernel_launch(void* const* d_in, const int* in_sizes, int n_in,
                              void* d_out, int out_size) {
    const float* x = (const float*)d_in[0];   // [16384, 128, 45] f32
    const float* w = (const float*)d_in[1];   // [128, 128, 5]   f32
    float* out = (float*)d_out;

    prep_w<<<80, 256>>>(w);
    sph_r15<<<8192, 128>>>(x, out);
}

// round 17
// speedup vs baseline: 1.2824x; 1.1462x over previous
#include <cuda_runtime.h>
#include <cstdint>

// SphConv, tf32 mma.sync. 256-thr CTA = 2 m-groups x 4 o32-warps, 2 batches.
// Hazard-safe 3-phase schedule (dump of region ending at row b corrupts only
// read-row b; every such read is scheduled in the same or an earlier phase):
//   ph1: g0=lg4(56),  g1=lg4(72,74)
//   ph2: g0=lg3(30,40), g1=lg2(12,14)
//   ph3: g0=lg1(2),   g1=lg0(0)
// Each x row ldsm-read by 4 warps (o32). bar.sync 0,256 inside each run.

#define NCOEF 45
#define BSTRIDE (128 * NCOEF)
#define XROW 132                        // MMA-phase row stride (528B)
#define TROW 133                        // transpose-phase row stride
#define SMEM_FLOATS 11970               // 90*133 -> 47880 B static

__device__ float4 g_wpB[5 * 16 * 8 * 32];

__global__ void prep_w(const float* __restrict__ w) {
    int idx  = blockIdx.x * blockDim.x + threadIdx.x;   // 20480 exactly
    int lane = idx & 31;
    int ks2  = (idx >> 5) & 7;
    int nb   = (idx >> 8) & 15;
    int lg   = idx >> 12;
    int o    = nb * 8 + (lane >> 2);
    int i0   = ks2 * 16 + (lane & 3);
    float l  = 2.0f * (float)lg;
    float s  = 6.28318530717958647692f *
               sqrtf(12.5663706143591729539f / (2.0f * l + 1.0f)) * (1.0f / 128.0f);
    float4 v;
    v.x = w[(o * 128 + i0) * 5 + lg] * s;
    v.y = w[(o * 128 + i0 + 4) * 5 + lg] * s;
    v.z = w[(o * 128 + i0 + 8) * 5 + lg] * s;
    v.w = w[(o * 128 + i0 + 12) * 5 + lg] * s;
    asm("cvt.rna.tf32.f32 %0, %0;" : "+f"(v.x));
    asm("cvt.rna.tf32.f32 %0, %0;" : "+f"(v.y));
    asm("cvt.rna.tf32.f32 %0, %0;" : "+f"(v.z));
    asm("cvt.rna.tf32.f32 %0, %0;" : "+f"(v.w));
    g_wpB[idx] = v;
}

__device__ __forceinline__ uint32_t smem_u32(const void* p) {
    uint32_t a;
    asm("{ .reg .u64 t; cvta.to.shared.u64 t, %1; cvt.u32.u64 %0, t; }" : "=r"(a) : "l"(p));
    return a;
}
__device__ __forceinline__ void ldsm4(uint32_t* r, uint32_t addr) {
    asm volatile("ldmatrix.sync.aligned.m8n8.x4.shared.b16 {%0,%1,%2,%3}, [%4];"
                 : "=r"(r[0]), "=r"(r[1]), "=r"(r[2]), "=r"(r[3]) : "r"(addr));
}
__device__ __forceinline__ void mma4(float* d, const uint32_t* a,
                                     uint32_t b0, uint32_t b1) {
    asm volatile(
        "mma.sync.aligned.m16n8k8.row.col.f32.tf32.tf32.f32 "
        "{%0,%1,%2,%3}, {%4,%5,%6,%7}, {%8,%9}, {%0,%1,%2,%3};"
        : "+f"(d[0]), "+f"(d[1]), "+f"(d[2]), "+f"(d[3])
        : "r"(a[0]), "r"(a[1]), "r"(a[2]), "r"(a[3]), "r"(b0), "r"(b1));
}
__device__ __forceinline__ void phase_bar() {
    asm volatile("bar.sync 0, 256;" ::: "memory");
}

// One lg-run: L (<=2) overlapping m16 blocks, o32 warp, K-eighth weight
// staging. Ends: full-CTA barrier + 133-stride predicated acc dump.
template <int LG, int L, int B0, int B1>
__device__ __forceinline__ void do_run(float* Xs, uint32_t sA,
                                       const float4* pw4, int ow, int lr, int lc) {
    constexpr int BASES[2] = {B0, B1};
    constexpr int GLO  = 2 * LG * LG - LG;
    constexpr int GLEN = 4 * LG + 1;
    constexpr int GLO2 = 2 * GLO;
    constexpr int GHI2 = GLO2 + 2 * GLEN;

    const float4* pw = pw4 + LG * 4096;

    float acc[L][4][4];
    #pragma unroll
    for (int j = 0; j < L; j++)
        #pragma unroll
        for (int nb = 0; nb < 4; nb++)
            #pragma unroll
            for (int e = 0; e < 4; e++) acc[j][nb][e] = 0.0f;

    #pragma unroll
    for (int s = 0; s < 8; s++) {
        float4 w4[4];
        #pragma unroll
        for (int nb = 0; nb < 4; nb++) w4[nb] = pw[nb * 256 + s * 32];

        #pragma unroll
        for (int j = 0; j < L; j++) {
            const uint32_t ab = sA + (uint32_t)(BASES[j] * (XROW * 4));
            uint32_t a0[4], a1[4];
            ldsm4(a0, ab + (uint32_t)((2 * s) * 32));
            ldsm4(a1, ab + (uint32_t)((2 * s + 1) * 32));
            #pragma unroll
            for (int nb = 0; nb < 4; nb++) {
                mma4(acc[j][nb], a0, __float_as_uint(w4[nb].x),
                                     __float_as_uint(w4[nb].y));
                mma4(acc[j][nb], a1, __float_as_uint(w4[nb].z),
                                     __float_as_uint(w4[nb].w));
            }
        }
    }

    phase_bar();   // all 8 warps rendezvous: phase reads done before dumps

    #pragma unroll
    for (int j = 0; j < L; j++) {
        #pragma unroll
        for (int hh = 0; hh < 2; hh++) {
            const int g = BASES[j] + lr + hh * 8;
            if (g >= GLO2 && g < GHI2) {
                float* p = Xs + g * TROW + ow * 32 + 2 * lc;
                #pragma unroll
                for (int nb = 0; nb < 4; nb++) {
                    p[nb * 8]     = acc[j][nb][hh * 2];
                    p[nb * 8 + 1] = acc[j][nb][hh * 2 + 1];
                }
            }
        }
    }
}

__global__ void __launch_bounds__(256, 3)
sph_r17(const float* __restrict__ x, float* __restrict__ out) {
    __shared__ __align__(16) float Xs[SMEM_FLOATS];
    __shared__ int rowTab[90];
    const int tid = threadIdx.x;
    const int lane = tid & 31, wid = tid >> 5;

    if (tid < 90) {
        const int b = tid / 45, k = tid - b * 45;
        const int lg = (k >= 28) ? 4 : (k >= 15) ? 3 : (k >= 6) ? 2
                                   : (k >= 1) ? 1 : 0;
        rowTab[tid] = k + (2 * lg * lg - lg) + b * (4 * lg + 1);
    }
    __syncthreads();

    // ---- fill: batched LDG (MLP 15) -> cvt.rna -> table-decoded STS ----
    {
        const float* src = x + (size_t)blockIdx.x * 2 * BSTRIDE + tid;
        int k = tid % 45, i = tid / 45, b_l = 0;
        #pragma unroll
        for (int batch = 0; batch < 3; batch++) {
            float v[15];
            #pragma unroll
            for (int u = 0; u < 15; u++)
                v[u] = __ldg(src + (size_t)(batch * 15 + u) * 256);
            #pragma unroll
            for (int u = 0; u < 15; u++) {
                float val = v[u];
                asm("cvt.rna.tf32.f32 %0, %0;" : "+f"(val));
                Xs[rowTab[b_l * 45 + k] * XROW + i] = val;
                k += 31; i += 5;                   // advance by 256
                if (k >= 45) { k -= 45; i += 1; }
                if (i >= 128) { i -= 128; b_l = 1; }
            }
        }
    }
    __syncthreads();

    const int lr = lane >> 2, lc = lane & 3;
    const int ow = wid & 3;             // o32 range
    const int mgrp = wid >> 2;          // m-group
    const uint32_t sbase = smem_u32(Xs);
    const uint32_t sA = sbase + (uint32_t)(((lane & 15) * XROW) * 4
                                           + ((lane >> 4) << 4));
    const float4* pw4 = g_wpB + (size_t)(ow * 4) * 256 + lane;

    // Hazard-safe schedule: dump(region ending at b) always in the same phase
    // as (or later than) the read of row b. Later-phase reads are strictly
    // below all earlier dumps.
    if (mgrp == 0) {
        do_run<4, 1, 56, 56>(Xs, sA, pw4, ow, lr, lc);   // ph1
        do_run<3, 2, 30, 40>(Xs, sA, pw4, ow, lr, lc);   // ph2
        do_run<1, 1, 2,  2 >(Xs, sA, pw4, ow, lr, lc);   // ph3
    } else {
        do_run<4, 2, 72, 74>(Xs, sA, pw4, ow, lr, lc);   // ph1
        do_run<2, 2, 12, 14>(Xs, sA, pw4, ow, lr, lc);   // ph2
        do_run<0, 1, 0,  0 >(Xs, sA, pw4, ow, lr, lc);   // ph3
    }
    __syncthreads();

    // ---- coalesced linear STG: warp owns batch (wid>>2), o-quarter (wid&3) ----
    {
        const int b = wid >> 2;
        const int o_base = (wid & 3) * 32;
        float* ob = out + (size_t)blockIdx.x * 2 * BSTRIDE
                    + (size_t)b * BSTRIDE + o_base * NCOEF;
        const int* tabB = rowTab + b * 45;
        int k = lane, o = 0;
        #pragma unroll 5
        for (int it = 0; it < 45; it++) {
            ob[it * 32 + lane] = Xs[tabB[k] * TROW + o_base + o];
            k += 32;
            if (k >= 45) { k -= 45; o += 1; }
        }
    }
}

extern "C" void kernel_launch(void* const* d_in, const int* in_sizes, int n_in,
                              void* d_out, int out_size) {
    const float* x = (const float*)d_in[0];   // [16384, 128, 45] f32
    const float* w = (const float*)d_in[1];   // [128, 128, 5]   f32
    float* out = (float*)d_out;

    prep_w<<<80, 256>>>(w);
    sph_r17<<<8192, 256>>>(x, out);
}